// round 13
// baseline (speedup 1.0000x reference)
#include <cuda_runtime.h>

#define D_MODEL 1024
#define HID     4096
#define N_KEYS  65536
#define TOPK    6

#define H_CHUNK 8
#define N_HCH   (HID / H_CHUNK)                // 512 blocks for k_qv

#define ROWS_PER_BLK 64
#define SC_BLOCKS    (N_KEYS / ROWS_PER_BLK)   // 1024
#define N_CAND       (SC_BLOCKS * TOPK)        // 6144
#define CAND_PER_THR (N_CAND / 256)            // 24

typedef unsigned long long u64;

// ---- scratch (no allocation allowed) ----
__device__ float g_q[HID];
__device__ float g_vpart[N_HCH * D_MODEL];
__device__ float g_v[D_MODEL];
__device__ float g_c;
__device__ u64   g_cand[N_CAND];
__device__ int   g_ctr;                        // zero-init; reset by last block

// sortable key: higher key <=> greater value, ties -> lower index wins
__device__ __forceinline__ u64 make_key(float v, int idx) {
    unsigned u = __float_as_uint(v);
    u = (u & 0x80000000u) ? ~u : (u | 0x80000000u);
    return ((u64)u << 32) | (unsigned)(~idx);
}
__device__ __forceinline__ int key_idx(u64 k) { return ~(unsigned)(k & 0xffffffffu); }

__device__ __forceinline__ u64 warp_max_u64(u64 k) {
#pragma unroll
    for (int o = 16; o; o >>= 1) {
        u64 other = __shfl_xor_sync(0xffffffffu, k, o);
        if (other > k) k = other;
    }
    return k;
}

// ---------------------------------------------------------------------------
// Fused: q[h] for this block's 8-row h-chunk (one warp per row), then the
// chunk's partial-v contribution. 512 blocks x 256 threads.
// ---------------------------------------------------------------------------
__global__ void __launch_bounds__(256) k_qv(const float* __restrict__ Wq,
                                            const float* __restrict__ query,
                                            const float* __restrict__ bq,
                                            const float* __restrict__ Wk) {
    __shared__ float sq[D_MODEL];
    __shared__ float sqr[H_CHUNK];
    int tid = threadIdx.x;
    int h0  = blockIdx.x * H_CHUNK;

    for (int i = tid; i < D_MODEL; i += 256) sq[i] = query[i];
    __syncthreads();

    int warp = tid >> 5, lane = tid & 31;
    const float4* Q = reinterpret_cast<const float4*>(sq);
    {
        int h = h0 + warp;                      // 8 warps x 1 row
        const float4* W = reinterpret_cast<const float4*>(Wq + (size_t)h * D_MODEL);
        float acc = 0.f;
#pragma unroll
        for (int j = 0; j < 8; j++) {
            float4 w = __ldcs(&W[lane + 32 * j]);
            float4 q = Q[lane + 32 * j];
            acc += w.x * q.x + w.y * q.y + w.z * q.z + w.w * q.w;
        }
#pragma unroll
        for (int off = 16; off; off >>= 1)
            acc += __shfl_down_sync(0xffffffffu, acc, off);
        if (lane == 0) {
            float qv = acc + bq[h];
            sqr[warp] = qv;
            g_q[h] = qv;
        }
    }
    __syncthreads();

    float acc0 = 0.f, acc1 = 0.f, acc2 = 0.f, acc3 = 0.f;
#pragma unroll
    for (int h = 0; h < H_CHUNK; h++) {
        const float* row = Wk + (size_t)(h0 + h) * D_MODEL;
        float qh = sqr[h];
        acc0 += __ldcs(&row[tid      ]) * qh;
        acc1 += __ldcs(&row[tid + 256]) * qh;
        acc2 += __ldcs(&row[tid + 512]) * qh;
        acc3 += __ldcs(&row[tid + 768]) * qh;
    }
    float* vp = g_vpart + (size_t)blockIdx.x * D_MODEL;
    vp[tid      ] = acc0;
    vp[tid + 256] = acc1;
    vp[tid + 512] = acc2;
    vp[tid + 768] = acc3;
}

// ---------------------------------------------------------------------------
// reduce 512 partials -> v (16 blocks x 64 d's x 4 group-slices);
// block 16 computes c = bk . q. Fixed summation order -> deterministic.
// ---------------------------------------------------------------------------
__global__ void __launch_bounds__(256) k_vreduce(const float* __restrict__ bk) {
    __shared__ float red[256];
    int tid = threadIdx.x;

    if (blockIdx.x < 16) {
        int dloc  = tid & 63;                   // 0..63
        int slice = tid >> 6;                   // 0..3
        int d     = blockIdx.x * 64 + dloc;
        float s = 0.f;
        int g0 = slice * (N_HCH / 4);
#pragma unroll 8
        for (int g = 0; g < N_HCH / 4; g++)
            s += g_vpart[(size_t)(g0 + g) * D_MODEL + d];
        red[tid] = s;
        __syncthreads();
        if (tid < 64)
            g_v[d] = red[tid] + red[tid + 64] + red[tid + 128] + red[tid + 192];
    } else {
        float s = 0.f;
        for (int h = tid; h < HID; h += 256) s += bk[h] * g_q[h];
        red[tid] = s;
        __syncthreads();
        for (int o = 128; o; o >>= 1) {
            if (tid < o) red[tid] += red[tid + o];
            __syncthreads();
        }
        if (tid == 0) g_c = red[0];
    }
}

// ---------------------------------------------------------------------------
// Fused scores + per-block top-6 + (last block only) global merge & mean.
// 1024 blocks x 256 threads, 64 rows/block.
// ---------------------------------------------------------------------------
__global__ void __launch_bounds__(256) k_scores_topk(const float* __restrict__ key_mat,
                                                     float* __restrict__ out) {
    __shared__ float sv[D_MODEL];
    __shared__ float ss[ROWS_PER_BLK];
    __shared__ int   isLast;
    __shared__ u64   swarp[8];
    __shared__ u64   swin;
    int tid = threadIdx.x;
    int warp = tid >> 5, lane = tid & 31;

    for (int i = tid; i < D_MODEL; i += 256) sv[i] = g_v[i];
    __syncthreads();

    int rowBase = blockIdx.x * ROWS_PER_BLK;
    const float4* V = reinterpret_cast<const float4*>(sv);
    float c = g_c;

#pragma unroll
    for (int it = 0; it < 8; it++) {
        int r = it * 8 + warp;
        const float4* K = reinterpret_cast<const float4*>(
            key_mat + (size_t)(rowBase + r) * D_MODEL);
        float acc = 0.f;
#pragma unroll
        for (int j = 0; j < 8; j++) {
            float4 k = __ldcs(&K[lane + 32 * j]);
            float4 v = V[lane + 32 * j];
            acc += k.x * v.x + k.y * v.y + k.z * v.z + k.w * v.w;
        }
#pragma unroll
        for (int off = 16; off; off >>= 1)
            acc += __shfl_down_sync(0xffffffffu, acc, off);
        if (lane == 0) ss[r] = acc + c;
    }
    __syncthreads();

    // warp 0: top-6 of 64 scores via bound trick (keys unique; pass t = max < bound)
    if (warp == 0) {
        u64 k0 = make_key(ss[lane],      rowBase + lane);
        u64 k1 = make_key(ss[lane + 32], rowBase + lane + 32);
        u64 bound = ~0ull;
#pragma unroll
        for (int t = 0; t < TOPK; t++) {
            u64 a = (k0 < bound) ? k0 : 0;
            u64 b = (k1 < bound) ? k1 : 0;
            u64 mine = (a > b) ? a : b;
            u64 win  = warp_max_u64(mine);
            if (lane == 0) g_cand[blockIdx.x * TOPK + t] = win;
            bound = win;
        }
    }

    // ---- last-block global merge ----
    __threadfence();
    if (tid == 0) {
        int done = atomicAdd(&g_ctr, 1);
        isLast = (done == SC_BLOCKS - 1);
        if (isLast) g_ctr = 0;                  // reset for next graph replay
    }
    __syncthreads();
    if (!isLast) return;
    __threadfence();                            // see all g_cand

    u64 bound = ~0ull;
    int topIdx[TOPK];
#pragma unroll
    for (int t = 0; t < TOPK; t++) {
        u64 best = 0;
#pragma unroll
        for (int j = 0; j < CAND_PER_THR; j++) {
            u64 kk = g_cand[tid + 256 * j];
            if (kk < bound && kk > best) best = kk;
        }
        best = warp_max_u64(best);
        if (lane == 0) swarp[warp] = best;
        __syncthreads();
        if (warp == 0) {
            u64 b = (lane < 8) ? swarp[lane] : 0;
            b = warp_max_u64(b);
            if (lane == 0) swin = b;
        }
        __syncthreads();
        bound = swin;
        topIdx[t] = key_idx(bound);
        __syncthreads();
    }

    // mean of the 6 selected rows; 256 threads x 4 columns
#pragma unroll
    for (int j = 0; j < 4; j++) {
        int d = tid + 256 * j;
        float s = 0.f;
#pragma unroll
        for (int t = 0; t < TOPK; t++)
            s += key_mat[(size_t)topIdx[t] * D_MODEL + d];
        out[d] = s * (1.0f / 6.0f);
    }
}

// ---------------------------------------------------------------------------
extern "C" void kernel_launch(void* const* d_in, const int* in_sizes, int n_in,
                              void* d_out, int out_size) {
    const float* query   = (const float*)d_in[0];
    const float* key_mat = (const float*)d_in[1];
    const float* Wq      = (const float*)d_in[2];
    const float* bq      = (const float*)d_in[3];
    const float* Wk      = (const float*)d_in[4];
    const float* bk      = (const float*)d_in[5];
    float* out = (float*)d_out;

    k_qv<<<N_HCH, 256>>>(Wq, query, bq, Wk);
    k_vreduce<<<17, 256>>>(bk);
    k_scores_topk<<<SC_BLOCKS, 256>>>(key_mat, out);
}

// round 14
// speedup vs baseline: 1.0080x; 1.0080x over previous
#include <cuda_runtime.h>

#define D_MODEL 1024
#define HID     4096
#define N_KEYS  65536
#define TOPK    6

#define H_CHUNK 8
#define N_HCH   (HID / H_CHUNK)                // 512 blocks for k_qv

#define ROWS_PER_BLK 64
#define SC_BLOCKS    (N_KEYS / ROWS_PER_BLK)   // 1024
#define N_CAND       (SC_BLOCKS * TOPK)        // 6144
#define CAND_PER_THR (N_CAND / 256)            // 24

typedef unsigned long long u64;

// ---- scratch (no allocation allowed) ----
__device__ float g_q[HID];
__device__ float g_vpart[N_HCH * D_MODEL];
__device__ float g_v[D_MODEL];
__device__ float g_c;
__device__ u64   g_cand[N_CAND];
__device__ int   g_ctr;                        // zero-init; reset by last block

// sortable key: higher key <=> greater value, ties -> lower index wins
__device__ __forceinline__ u64 make_key(float v, int idx) {
    unsigned u = __float_as_uint(v);
    u = (u & 0x80000000u) ? ~u : (u | 0x80000000u);
    return ((u64)u << 32) | (unsigned)(~idx);
}
__device__ __forceinline__ int key_idx(u64 k) { return ~(unsigned)(k & 0xffffffffu); }

__device__ __forceinline__ u64 warp_max_u64(u64 k) {
#pragma unroll
    for (int o = 16; o; o >>= 1) {
        u64 other = __shfl_xor_sync(0xffffffffu, k, o);
        if (other > k) k = other;
    }
    return k;
}

// ---------------------------------------------------------------------------
// Fused: q[h] for this block's 8-row h-chunk (one warp per row), then the
// chunk's partial-v contribution. 512 blocks x 256 threads.
// ---------------------------------------------------------------------------
__global__ void __launch_bounds__(256) k_qv(const float* __restrict__ Wq,
                                            const float* __restrict__ query,
                                            const float* __restrict__ bq,
                                            const float* __restrict__ Wk) {
    __shared__ float sq[D_MODEL];
    __shared__ float sqr[H_CHUNK];
    int tid = threadIdx.x;
    int h0  = blockIdx.x * H_CHUNK;

    for (int i = tid; i < D_MODEL; i += 256) sq[i] = query[i];
    __syncthreads();

    int warp = tid >> 5, lane = tid & 31;
    const float4* Q = reinterpret_cast<const float4*>(sq);
    {
        int h = h0 + warp;                      // 8 warps x 1 row
        const float4* W = reinterpret_cast<const float4*>(Wq + (size_t)h * D_MODEL);
        float acc = 0.f;
#pragma unroll
        for (int j = 0; j < 8; j++) {
            float4 w = __ldcs(&W[lane + 32 * j]);
            float4 q = Q[lane + 32 * j];
            acc += w.x * q.x + w.y * q.y + w.z * q.z + w.w * q.w;
        }
#pragma unroll
        for (int off = 16; off; off >>= 1)
            acc += __shfl_down_sync(0xffffffffu, acc, off);
        if (lane == 0) {
            float qv = acc + bq[h];
            sqr[warp] = qv;
            g_q[h] = qv;
        }
    }
    __syncthreads();

    float acc0 = 0.f, acc1 = 0.f, acc2 = 0.f, acc3 = 0.f;
#pragma unroll
    for (int h = 0; h < H_CHUNK; h++) {
        const float* row = Wk + (size_t)(h0 + h) * D_MODEL;
        float qh = sqr[h];
        acc0 += __ldcs(&row[tid      ]) * qh;
        acc1 += __ldcs(&row[tid + 256]) * qh;
        acc2 += __ldcs(&row[tid + 512]) * qh;
        acc3 += __ldcs(&row[tid + 768]) * qh;
    }
    float* vp = g_vpart + (size_t)blockIdx.x * D_MODEL;
    vp[tid      ] = acc0;
    vp[tid + 256] = acc1;
    vp[tid + 512] = acc2;
    vp[tid + 768] = acc3;
}

// ---------------------------------------------------------------------------
// reduce 512 partials -> v (16 blocks x 64 d's x 4 group-slices);
// block 16 computes c = bk . q. Fixed summation order -> deterministic.
// ---------------------------------------------------------------------------
__global__ void __launch_bounds__(256) k_vreduce(const float* __restrict__ bk) {
    __shared__ float red[256];
    int tid = threadIdx.x;

    if (blockIdx.x < 16) {
        int dloc  = tid & 63;                   // 0..63
        int slice = tid >> 6;                   // 0..3
        int d     = blockIdx.x * 64 + dloc;
        float s = 0.f;
        int g0 = slice * (N_HCH / 4);
#pragma unroll 8
        for (int g = 0; g < N_HCH / 4; g++)
            s += g_vpart[(size_t)(g0 + g) * D_MODEL + d];
        red[tid] = s;
        __syncthreads();
        if (tid < 64)
            g_v[d] = red[tid] + red[tid + 64] + red[tid + 128] + red[tid + 192];
    } else {
        float s = 0.f;
        for (int h = tid; h < HID; h += 256) s += bk[h] * g_q[h];
        red[tid] = s;
        __syncthreads();
        for (int o = 128; o; o >>= 1) {
            if (tid < o) red[tid] += red[tid + o];
            __syncthreads();
        }
        if (tid == 0) g_c = red[0];
    }
}

// ---------------------------------------------------------------------------
// Fused scores + per-block top-6 + (last block only) global merge & mean.
// 1024 blocks x 256 threads, 64 rows/block.
// ---------------------------------------------------------------------------
__global__ void __launch_bounds__(256) k_scores_topk(const float* __restrict__ key_mat,
                                                     float* __restrict__ out) {
    __shared__ float sv[D_MODEL];
    __shared__ float ss[ROWS_PER_BLK];
    __shared__ int   isLast;
    __shared__ u64   swarp[8];
    __shared__ u64   swin;
    int tid = threadIdx.x;
    int warp = tid >> 5, lane = tid & 31;

    for (int i = tid; i < D_MODEL; i += 256) sv[i] = g_v[i];
    __syncthreads();

    int rowBase = blockIdx.x * ROWS_PER_BLK;
    const float4* V = reinterpret_cast<const float4*>(sv);
    float c = g_c;

#pragma unroll
    for (int it = 0; it < 8; it++) {
        int r = it * 8 + warp;
        const float4* K = reinterpret_cast<const float4*>(
            key_mat + (size_t)(rowBase + r) * D_MODEL);
        float acc = 0.f;
#pragma unroll
        for (int j = 0; j < 8; j++) {
            float4 k = __ldcs(&K[lane + 32 * j]);
            float4 v = V[lane + 32 * j];
            acc += k.x * v.x + k.y * v.y + k.z * v.z + k.w * v.w;
        }
#pragma unroll
        for (int off = 16; off; off >>= 1)
            acc += __shfl_down_sync(0xffffffffu, acc, off);
        if (lane == 0) ss[r] = acc + c;
    }
    __syncthreads();

    // warp 0: top-6 of 64 scores via bound trick (keys unique; pass t = max < bound)
    if (warp == 0) {
        u64 k0 = make_key(ss[lane],      rowBase + lane);
        u64 k1 = make_key(ss[lane + 32], rowBase + lane + 32);
        u64 bound = ~0ull;
#pragma unroll
        for (int t = 0; t < TOPK; t++) {
            u64 a = (k0 < bound) ? k0 : 0;
            u64 b = (k1 < bound) ? k1 : 0;
            u64 mine = (a > b) ? a : b;
            u64 win  = warp_max_u64(mine);
            if (lane == 0) g_cand[blockIdx.x * TOPK + t] = win;
            bound = win;
        }
    }

    // ---- last-block global merge ----
    __threadfence();
    if (tid == 0) {
        int done = atomicAdd(&g_ctr, 1);
        isLast = (done == SC_BLOCKS - 1);
        if (isLast) g_ctr = 0;                  // reset for next graph replay
    }
    __syncthreads();
    if (!isLast) return;
    __threadfence();                            // see all g_cand

    u64 bound = ~0ull;
    int topIdx[TOPK];
#pragma unroll
    for (int t = 0; t < TOPK; t++) {
        u64 best = 0;
#pragma unroll
        for (int j = 0; j < CAND_PER_THR; j++) {
            u64 kk = g_cand[tid + 256 * j];
            if (kk < bound && kk > best) best = kk;
        }
        best = warp_max_u64(best);
        if (lane == 0) swarp[warp] = best;
        __syncthreads();
        if (warp == 0) {
            u64 b = (lane < 8) ? swarp[lane] : 0;
            b = warp_max_u64(b);
            if (lane == 0) swin = b;
        }
        __syncthreads();
        bound = swin;
        topIdx[t] = key_idx(bound);
        __syncthreads();
    }

    // mean of the 6 selected rows; 256 threads x 4 columns
#pragma unroll
    for (int j = 0; j < 4; j++) {
        int d = tid + 256 * j;
        float s = 0.f;
#pragma unroll
        for (int t = 0; t < TOPK; t++)
            s += key_mat[(size_t)topIdx[t] * D_MODEL + d];
        out[d] = s * (1.0f / 6.0f);
    }
}

// ---------------------------------------------------------------------------
extern "C" void kernel_launch(void* const* d_in, const int* in_sizes, int n_in,
                              void* d_out, int out_size) {
    const float* query   = (const float*)d_in[0];
    const float* key_mat = (const float*)d_in[1];
    const float* Wq      = (const float*)d_in[2];
    const float* bq      = (const float*)d_in[3];
    const float* Wk      = (const float*)d_in[4];
    const float* bk      = (const float*)d_in[5];
    float* out = (float*)d_out;

    k_qv<<<N_HCH, 256>>>(Wq, query, bq, Wk);
    k_vreduce<<<17, 256>>>(bk);
    k_scores_topk<<<SC_BLOCKS, 256>>>(key_mat, out);
}

// round 15
// speedup vs baseline: 1.0116x; 1.0036x over previous
#include <cuda_runtime.h>

#define D_MODEL 1024
#define HID     4096
#define N_KEYS  65536
#define TOPK    6

#define H_CHUNK 8
#define N_HCH   (HID / H_CHUNK)                // 512 blocks for k_qv

#define ROWS_PER_BLK 64
#define SC_BLOCKS    (N_KEYS / ROWS_PER_BLK)   // 1024
#define N_CAND       (SC_BLOCKS * TOPK)        // 6144
#define CAND_PER_THR (N_CAND / 256)            // 24

typedef unsigned long long u64;

// ---- scratch (no allocation allowed) ----
__device__ float g_q[HID];
__device__ float g_vpart[N_HCH * D_MODEL];
__device__ float g_v[D_MODEL];
__device__ float g_c;
__device__ u64   g_cand[N_CAND];
__device__ int   g_ctr;                        // zero-init; reset by last block

// sortable key: higher key <=> greater value, ties -> lower index wins
__device__ __forceinline__ u64 make_key(float v, int idx) {
    unsigned u = __float_as_uint(v);
    u = (u & 0x80000000u) ? ~u : (u | 0x80000000u);
    return ((u64)u << 32) | (unsigned)(~idx);
}
__device__ __forceinline__ int key_idx(u64 k) { return ~(unsigned)(k & 0xffffffffu); }

__device__ __forceinline__ u64 warp_max_u64(u64 k) {
#pragma unroll
    for (int o = 16; o; o >>= 1) {
        u64 other = __shfl_xor_sync(0xffffffffu, k, o);
        if (other > k) k = other;
    }
    return k;
}

// ---------------------------------------------------------------------------
// Fused: q[h] for this block's 8-row h-chunk (one warp per row), then the
// chunk's partial-v contribution. 512 blocks x 256 threads.
// ---------------------------------------------------------------------------
__global__ void __launch_bounds__(256) k_qv(const float* __restrict__ Wq,
                                            const float* __restrict__ query,
                                            const float* __restrict__ bq,
                                            const float* __restrict__ Wk) {
    __shared__ float sq[D_MODEL];
    __shared__ float sqr[H_CHUNK];
    int tid = threadIdx.x;
    int h0  = blockIdx.x * H_CHUNK;

    for (int i = tid; i < D_MODEL; i += 256) sq[i] = query[i];
    __syncthreads();

    int warp = tid >> 5, lane = tid & 31;
    const float4* Q = reinterpret_cast<const float4*>(sq);
    {
        int h = h0 + warp;                      // 8 warps x 1 row
        const float4* W = reinterpret_cast<const float4*>(Wq + (size_t)h * D_MODEL);
        float acc = 0.f;
#pragma unroll
        for (int j = 0; j < 8; j++) {
            float4 w = __ldcs(&W[lane + 32 * j]);
            float4 q = Q[lane + 32 * j];
            acc += w.x * q.x + w.y * q.y + w.z * q.z + w.w * q.w;
        }
#pragma unroll
        for (int off = 16; off; off >>= 1)
            acc += __shfl_down_sync(0xffffffffu, acc, off);
        if (lane == 0) {
            float qv = acc + bq[h];
            sqr[warp] = qv;
            g_q[h] = qv;
        }
    }
    __syncthreads();

    float acc0 = 0.f, acc1 = 0.f, acc2 = 0.f, acc3 = 0.f;
#pragma unroll
    for (int h = 0; h < H_CHUNK; h++) {
        const float* row = Wk + (size_t)(h0 + h) * D_MODEL;
        float qh = sqr[h];
        acc0 += __ldcs(&row[tid      ]) * qh;
        acc1 += __ldcs(&row[tid + 256]) * qh;
        acc2 += __ldcs(&row[tid + 512]) * qh;
        acc3 += __ldcs(&row[tid + 768]) * qh;
    }
    float* vp = g_vpart + (size_t)blockIdx.x * D_MODEL;
    vp[tid      ] = acc0;
    vp[tid + 256] = acc1;
    vp[tid + 512] = acc2;
    vp[tid + 768] = acc3;
}

// ---------------------------------------------------------------------------
// reduce 512 partials -> v (16 blocks x 64 d's x 4 group-slices);
// block 16 computes c = bk . q. Fixed summation order -> deterministic.
// ---------------------------------------------------------------------------
__global__ void __launch_bounds__(256) k_vreduce(const float* __restrict__ bk) {
    __shared__ float red[256];
    int tid = threadIdx.x;

    if (blockIdx.x < 16) {
        int dloc  = tid & 63;                   // 0..63
        int slice = tid >> 6;                   // 0..3
        int d     = blockIdx.x * 64 + dloc;
        float s = 0.f;
        int g0 = slice * (N_HCH / 4);
#pragma unroll 8
        for (int g = 0; g < N_HCH / 4; g++)
            s += g_vpart[(size_t)(g0 + g) * D_MODEL + d];
        red[tid] = s;
        __syncthreads();
        if (tid < 64)
            g_v[d] = red[tid] + red[tid + 64] + red[tid + 128] + red[tid + 192];
    } else {
        float s = 0.f;
        for (int h = tid; h < HID; h += 256) s += bk[h] * g_q[h];
        red[tid] = s;
        __syncthreads();
        for (int o = 128; o; o >>= 1) {
            if (tid < o) red[tid] += red[tid + o];
            __syncthreads();
        }
        if (tid == 0) g_c = red[0];
    }
}

// ---------------------------------------------------------------------------
// Fused scores + per-block top-6 + (last block only) global merge & mean.
// 1024 blocks x 256 threads, 64 rows/block.
// ---------------------------------------------------------------------------
__global__ void __launch_bounds__(256) k_scores_topk(const float* __restrict__ key_mat,
                                                     float* __restrict__ out) {
    __shared__ float sv[D_MODEL];
    __shared__ float ss[ROWS_PER_BLK];
    __shared__ int   isLast;
    __shared__ u64   swarp[8];
    __shared__ u64   swin;
    int tid = threadIdx.x;
    int warp = tid >> 5, lane = tid & 31;

    for (int i = tid; i < D_MODEL; i += 256) sv[i] = g_v[i];
    __syncthreads();

    int rowBase = blockIdx.x * ROWS_PER_BLK;
    const float4* V = reinterpret_cast<const float4*>(sv);
    float c = g_c;

#pragma unroll
    for (int it = 0; it < 8; it++) {
        int r = it * 8 + warp;
        const float4* K = reinterpret_cast<const float4*>(
            key_mat + (size_t)(rowBase + r) * D_MODEL);
        float acc = 0.f;
#pragma unroll
        for (int j = 0; j < 8; j++) {
            float4 k = __ldcs(&K[lane + 32 * j]);
            float4 v = V[lane + 32 * j];
            acc += k.x * v.x + k.y * v.y + k.z * v.z + k.w * v.w;
        }
#pragma unroll
        for (int off = 16; off; off >>= 1)
            acc += __shfl_down_sync(0xffffffffu, acc, off);
        if (lane == 0) ss[r] = acc + c;
    }
    __syncthreads();

    // warp 0: top-6 of 64 scores via bound trick (keys unique; pass t = max < bound)
    if (warp == 0) {
        u64 k0 = make_key(ss[lane],      rowBase + lane);
        u64 k1 = make_key(ss[lane + 32], rowBase + lane + 32);
        u64 bound = ~0ull;
#pragma unroll
        for (int t = 0; t < TOPK; t++) {
            u64 a = (k0 < bound) ? k0 : 0;
            u64 b = (k1 < bound) ? k1 : 0;
            u64 mine = (a > b) ? a : b;
            u64 win  = warp_max_u64(mine);
            if (lane == 0) g_cand[blockIdx.x * TOPK + t] = win;
            bound = win;
        }
    }

    // ---- last-block global merge ----
    __threadfence();
    if (tid == 0) {
        int done = atomicAdd(&g_ctr, 1);
        isLast = (done == SC_BLOCKS - 1);
        if (isLast) g_ctr = 0;                  // reset for next graph replay
    }
    __syncthreads();
    if (!isLast) return;
    __threadfence();                            // see all g_cand

    u64 bound = ~0ull;
    int topIdx[TOPK];
#pragma unroll
    for (int t = 0; t < TOPK; t++) {
        u64 best = 0;
#pragma unroll
        for (int j = 0; j < CAND_PER_THR; j++) {
            u64 kk = g_cand[tid + 256 * j];
            if (kk < bound && kk > best) best = kk;
        }
        best = warp_max_u64(best);
        if (lane == 0) swarp[warp] = best;
        __syncthreads();
        if (warp == 0) {
            u64 b = (lane < 8) ? swarp[lane] : 0;
            b = warp_max_u64(b);
            if (lane == 0) swin = b;
        }
        __syncthreads();
        bound = swin;
        topIdx[t] = key_idx(bound);
        __syncthreads();
    }

    // mean of the 6 selected rows; 256 threads x 4 columns
#pragma unroll
    for (int j = 0; j < 4; j++) {
        int d = tid + 256 * j;
        float s = 0.f;
#pragma unroll
        for (int t = 0; t < TOPK; t++)
            s += key_mat[(size_t)topIdx[t] * D_MODEL + d];
        out[d] = s * (1.0f / 6.0f);
    }
}

// ---------------------------------------------------------------------------
extern "C" void kernel_launch(void* const* d_in, const int* in_sizes, int n_in,
                              void* d_out, int out_size) {
    const float* query   = (const float*)d_in[0];
    const float* key_mat = (const float*)d_in[1];
    const float* Wq      = (const float*)d_in[2];
    const float* bq      = (const float*)d_in[3];
    const float* Wk      = (const float*)d_in[4];
    const float* bk      = (const float*)d_in[5];
    float* out = (float*)d_out;

    k_qv<<<N_HCH, 256>>>(Wq, query, bq, Wk);
    k_vreduce<<<17, 256>>>(bk);
    k_scores_topk<<<SC_BLOCKS, 256>>>(key_mat, out);
}